// round 8
// baseline (speedup 1.0000x reference)
#include <cuda_runtime.h>
#include <math.h>
#include <float.h>

#define BN 8
#define H 480
#define W 640
#define OH 120
#define OW 160
#define CH 128
#define NP 192

typedef unsigned long long u64;

// ---------------- scratch ----------------
__device__ float d_cellval[BN*256];
__device__ int   d_cellxy[BN*256];
__device__ int   d_selxy[BN*NP];
// channel-last fmap copy: [b][oy][ox][ch]
__device__ float d_cl[(size_t)BN*OH*OW*CH];

// ---------------- f32x2 helpers ----------------
__device__ __forceinline__ u64 pack2(float lo, float hi) {
    u64 r; asm("mov.b64 %0, {%1, %2};" : "=l"(r) : "f"(lo), "f"(hi)); return r;
}
__device__ __forceinline__ void unpack2(u64 v, float& lo, float& hi) {
    asm("mov.b64 {%0, %1}, %2;" : "=f"(lo), "=f"(hi) : "l"(v));
}
__device__ __forceinline__ u64 ffma2(u64 a, u64 b, u64 c) {
    u64 d; asm("fma.rn.f32x2 %0, %1, %2, %3;" : "=l"(d) : "l"(a), "l"(b), "l"(c)); return d;
}

// ================= K1: fused harris + per-cell argmax =================
__global__ __launch_bounds__(256) void k_harris(const float* __restrict__ frame) {
    __shared__ float sf[37][48];
    __shared__ float shxx[36][40], shyy[36][40], shxy[36][40];
    __shared__ float sv[256];
    __shared__ int   si[256];

    int blk = blockIdx.x;
    int b = blk >> 8, cell = blk & 255;
    int gh = cell >> 4, gw = cell & 15;
    int gx0 = gw * 40, gy0 = gh * 30;
    int X0 = gx0 - 3, Y0 = gy0 - 3;
    const float* f = frame + (size_t)b * H * W;
    int tid = threadIdx.x;

    for (int i = tid; i < 37 * 47; i += 256) {
        int r = i / 47, c = i - r * 47;
        int x = X0 + c, y = Y0 + r;
        sf[r][c] = (x >= 0 && x < W && y >= 0 && y < H) ? f[y * W + x] : 0.f;
    }
    __syncthreads();

    for (int i = tid; i < 36 * 40; i += 256) {
        int r = i / 40, c = i - r * 40;
        int y = Y0 + r;
        float a = 0.f, bb = 0.f, cc2 = 0.f;
        if (y >= 0 && y < H) {
            bool ylast = (y == H - 1);
            #pragma unroll
            for (int k = 0; k < 7; k++) {
                int cw = c + k;
                int x = X0 + cw;
                if (x >= 0 && x < W) {
                    float dx = (x < W - 1) ? (sf[r][cw+1] - sf[r][cw])
                                           : (sf[r][cw-1] - sf[r][cw-2]);
                    float dy = !ylast ? (sf[r+1][cw] - sf[r][cw])
                                      : (sf[r-1][cw] - sf[r-2][cw]);
                    a   = fmaf(dx, dx, a);
                    bb  = fmaf(dy, dy, bb);
                    cc2 = fmaf(dx, dy, cc2);
                }
            }
        }
        shxx[r][c] = a; shyy[r][c] = bb; shxy[r][c] = cc2;
    }
    __syncthreads();

    float bv = -FLT_MAX;
    int   bi = 0x7FFFFFFF;
    for (int fi = tid; fi < 1200; fi += 256) {
        int py = fi / 40, px = fi - py * 40;
        float a = 0.f, bb = 0.f, cc = 0.f;
        #pragma unroll
        for (int k = 0; k < 7; k++) {
            a  += shxx[py + k][px];
            bb += shyy[py + k][px];
            cc += shxy[py + k][px];
        }
        float Ixx = a / 49.0f, Iyy = bb / 49.0f, Ixy = cc / 49.0f;
        float g = (Ixx * Iyy - Ixy * Ixy) / (Ixx + Iyy + 1e-8f);
        if (g > bv) { bv = g; bi = fi; }
    }
    sv[tid] = bv; si[tid] = bi;
    __syncthreads();
    for (int s = 128; s > 0; s >>= 1) {
        if (tid < s) {
            float v2 = sv[tid + s]; int i2 = si[tid + s];
            if (v2 > sv[tid] || (v2 == sv[tid] && i2 < si[tid])) { sv[tid] = v2; si[tid] = i2; }
        }
        __syncthreads();
    }
    if (tid == 0) {
        int fi = si[0];
        int py = fi / 40, px = fi - py * 40;
        d_cellval[blk] = sv[0];
        d_cellxy[blk]  = ((gy0 + py) << 16) | (gx0 + px);
    }
}

// ================= K2: top-192 by rank count (stable) =================
__global__ void k_topk(float* __restrict__ out_coords) {
    __shared__ float sv[256];
    __shared__ int   sxy[256];
    int b = blockIdx.x, i = threadIdx.x;
    sv[i]  = d_cellval[b*256 + i];
    sxy[i] = d_cellxy[b*256 + i];
    __syncthreads();
    float v = sv[i];
    int rank = 0;
    #pragma unroll 8
    for (int j = 0; j < 256; j++) {
        float vj = sv[j];
        rank += (vj > v) || (vj == v && j < i);
    }
    if (rank < NP) {
        int xy = sxy[i];
        int x = xy & 0xFFFF, y = xy >> 16;
        out_coords[((size_t)b*NP + rank)*2 + 0] = (float)x;
        out_coords[((size_t)b*NP + rank)*2 + 1] = (float)y;
        d_selxy[b*NP + rank] = xy;
    }
}

// ================= K3: conv v8 — 4-row tiles, no wprep =================
// Block 128 thr = 4 warps; warp = output row oyr (0..3). Lane owns channel
// pairs pA=lane (ch 0..63), pB=32+lane (ch 64..127) x 16 px.
// Raw weights loaded coalesced into smem [ch][tap]; pairs built per-ky via
// 2x LDS.32 (2-way conflict only). Epilogue: d_cl coalesced + smem-overlay
// staged fmap write (px-major stride 130, conflict-free).
#define SO_STRIDE 130

__global__ __launch_bounds__(128, 3) void k_conv(
    const float* __restrict__ frame,
    const float* __restrict__ wf,
    const float* __restrict__ bf,
    float* __restrict__ fmap)
{
    __shared__ __align__(16) unsigned char s_mem[35424];
    float* s_wraw = (float*)s_mem;                    // 6272 floats = 25088 B
    u64*   s_in   = (u64*)(s_mem + 25088);            // 19*68 u64 = 10336 B
    float* s_out  = (float*)s_mem;                    // overlay: 4*16*130 = 33280 B

    int tid  = threadIdx.x;
    int lane = tid & 31;
    int oyr  = tid >> 5;

    int ox0 = blockIdx.x * 16;
    int oy0 = blockIdx.y * 4;
    int b   = blockIdx.z;
    const float* f = frame + (size_t)b * H * W;
    int row0 = oy0 * 4 - 3, col0 = ox0 * 4 - 3;

    // coalesced raw-weight copy
    for (int i = tid; i < CH * 49; i += 128) s_wraw[i] = __ldg(wf + i);
    // input window: 19 rows x 67 cols, duplicated (v,v) pairs
    for (int i = tid; i < 19 * 67; i += 128) {
        int r = i / 67, c = i - r * 67;
        int y = row0 + r, x = col0 + c;
        float v = (y >= 0 && y < H && x >= 0 && x < W) ? f[(size_t)y*W + x] : 0.f;
        s_in[r * 68 + c] = pack2(v, v);
    }
    int cA = 2 * lane, cB = 64 + 2 * lane;
    u64 biasA = pack2(__ldg(bf + cA), __ldg(bf + cA + 1));
    u64 biasB = pack2(__ldg(bf + cB), __ldg(bf + cB + 1));
    __syncthreads();

    u64 accA[16], accB[16];
    #pragma unroll
    for (int i = 0; i < 16; i++) { accA[i] = biasA; accB[i] = biasB; }

    #pragma unroll 1
    for (int ky = 0; ky < 7; ky++) {
        const float* wb = s_wraw + ky * 7;
        u64 wkA[7], wkB[7];
        #pragma unroll
        for (int kx = 0; kx < 7; kx++) {
            wkA[kx] = pack2(wb[cA*49 + kx], wb[(cA+1)*49 + kx]);
            wkB[kx] = pack2(wb[cB*49 + kx], wb[(cB+1)*49 + kx]);
        }
        const u64* inp = s_in + (oyr * 4 + ky) * 68;
        #pragma unroll
        for (int c = 0; c < 67; c++) {
            u64 v = inp[c];
            int kx1 = c & 3, px1 = c >> 2;
            if (px1 < 16) {
                accA[px1] = ffma2(v, wkA[kx1], accA[px1]);
                accB[px1] = ffma2(v, wkB[kx1], accB[px1]);
            }
            if (kx1 < 3 && c >= 4) {
                int px2 = px1 - 1, kx2 = kx1 + 4;
                accA[px2] = ffma2(v, wkA[kx2], accA[px2]);
                accB[px2] = ffma2(v, wkB[kx2], accB[px2]);
            }
        }
    }

    // relu + channel-last store (coalesced 256B segments per warp per px)
    int oy = oy0 + oyr;
    float loA[16], hiA[16], loB[16], hiB[16];
    #pragma unroll
    for (int px = 0; px < 16; px++) {
        float a0, a1;
        unpack2(accA[px], a0, a1); loA[px] = fmaxf(a0, 0.f); hiA[px] = fmaxf(a1, 0.f);
        unpack2(accB[px], a0, a1); loB[px] = fmaxf(a0, 0.f); hiB[px] = fmaxf(a1, 0.f);
        u64* clp = (u64*)(d_cl + (((size_t)(b*OH + oy))*OW + ox0 + px) * CH);
        clp[lane]      = pack2(loA[px], hiA[px]);
        clp[32 + lane] = pack2(loB[px], hiB[px]);
    }

    // stage required layout (px-major, conflict-free u64 writes)
    __syncthreads();
    #pragma unroll
    for (int px = 0; px < 16; px++) {
        u64* po = (u64*)(s_out + (oyr*16 + px) * SO_STRIDE);
        po[lane]      = pack2(loA[px], hiA[px]);
        po[32 + lane] = pack2(loB[px], hiB[px]);
    }
    __syncthreads();

    // coalesced copy-out
    for (int i = tid; i < 4 * 128 * 16; i += 128) {
        int px = i & 15;
        int ch = (i >> 4) & 127;
        int r  = i >> 11;
        fmap[(((size_t)(b*CH + ch)) * OH + (oy0 + r)) * OW + ox0 + px] =
            s_out[(r*16 + px) * SO_STRIDE + ch];
    }
}

// ================= K4: patches_f — channel-last coalesced gather =============
__global__ __launch_bounds__(128) void k_patches_f(float* __restrict__ out) {
    __shared__ float s[CH * 49];
    int bp = blockIdx.x;
    int b  = bp / NP;
    int c  = threadIdx.x;
    int xy = d_selxy[bp];
    float fx = (float)(xy & 0xFFFF) * 0.25f;
    float fy = (float)(xy >> 16)    * 0.25f;
    int x0 = (int)floorf(fx);
    int y0 = (int)floorf(fy);
    float wx = fx - (float)x0, wy = fy - (float)y0;
    int gx0 = x0 - 3, gy0 = y0 - 3;

    const float* base = d_cl + (size_t)b * OH * OW * CH + c;

    float v[64];
    #pragma unroll
    for (int pt = 0; pt < 64; pt++) {
        int yy = pt >> 3, xx = pt & 7;
        int gy = gy0 + yy, gx = gx0 + xx;
        bool ok = (gx >= 0) & (gx < OW) & (gy >= 0) & (gy < OH);
        v[pt] = ok ? __ldg(base + ((size_t)gy * OW + gx) * CH) : 0.f;
    }

    float w00 = (1.f - wx) * (1.f - wy);
    float w10 = wx * (1.f - wy);
    float w01 = (1.f - wx) * wy;
    float w11 = wx * wy;

    #pragma unroll
    for (int j = 0; j < 7; j++) {
        #pragma unroll
        for (int i = 0; i < 7; i++) {
            float acc = v[j*8 + i]       * w00
                      + v[j*8 + i + 1]   * w10
                      + v[(j+1)*8 + i]   * w01
                      + v[(j+1)*8 + i+1] * w11;
            s[c * 49 + (j*7 + i)] = acc;
        }
    }
    __syncthreads();

    float* o = out + (size_t)bp * (CH * 49);
    for (int k = threadIdx.x; k < CH * 49; k += 128)
        o[k] = s[k];
}

// ================= K5: patches_c — smem-staged weights =================
__global__ __launch_bounds__(128) void k_patches_c(
    const float* __restrict__ frame,
    const float* __restrict__ wc,
    const float* __restrict__ bc,
    float* __restrict__ out)
{
    __shared__ float s_w[CH * 49];
    __shared__ float s_in[121];
    int bp = blockIdx.x;
    int b  = bp / NP;
    int c  = threadIdx.x;
    int xy = d_selxy[bp];
    float fx = (float)(xy & 0xFFFF) * 0.25f;
    float fy = (float)(xy >> 16)    * 0.25f;
    int x0 = (int)floorf(fx);
    int y0 = (int)floorf(fy);
    float wx = fx - (float)x0, wy = fy - (float)y0;

    const float* f = frame + (size_t)b * H * W;
    int row0 = y0 * 4 - 3, col0 = x0 * 4 - 3;
    for (int i = threadIdx.x; i < CH * 49; i += 128) s_w[i] = __ldg(wc + i);
    for (int i = threadIdx.x; i < 121; i += 128) {
        int r = i / 11, cc = i - r * 11;
        int yyy = row0 + r, xxx = col0 + cc;
        s_in[i] = (yyy >= 0 && yyy < H && xxx >= 0 && xxx < W) ? f[yyy*W + xxx] : 0.f;
    }
    float bias = __ldg(bc + c);
    __syncthreads();

    float wreg[49];
    #pragma unroll
    for (int i = 0; i < 49; i++) wreg[i] = s_w[c*49 + i];

    float wts[4] = { (1.f-wx)*(1.f-wy), wx*(1.f-wy), (1.f-wx)*wy, wx*wy };
    float acc = 0.f;
    #pragma unroll
    for (int n = 0; n < 4; n++) {
        int dxn = n & 1, dyn = n >> 1;
        int xi = x0 + dxn, yi = y0 + dyn;
        if (xi < OW && yi < OH) {
            float v = bias;
            #pragma unroll
            for (int ky = 0; ky < 7; ky++)
                #pragma unroll
                for (int kx = 0; kx < 7; kx++)
                    v = fmaf(s_in[(dyn*4 + ky)*11 + (dxn*4 + kx)], wreg[ky*7 + kx], v);
            v = fmaxf(v, 0.f);
            acc += v * wts[n];
        }
    }
    out[(size_t)bp * CH + c] = acc;
}

// ---------------- launch: fork-join across two streams ---------------------------
extern "C" void kernel_launch(void* const* d_in, const int* in_sizes, int n_in,
                              void* d_out, int out_size) {
    const float* frame = (const float*)d_in[0];
    const float* w_f   = (const float*)d_in[1];
    const float* b_f   = (const float*)d_in[2];
    const float* w_c   = (const float*)d_in[3];
    const float* b_c   = (const float*)d_in[4];

    float* out        = (float*)d_out;
    float* out_coords = out;                                   // 8*192*2
    float* out_pf     = out + 3072;                            // 8*192*128*49
    float* out_pc     = out + 3072 + 9633792;                  // 8*192*128
    float* out_fmap   = out + 3072 + 9633792 + 196608;         // 8*128*120*160

    static cudaStream_t s1 = 0;
    static cudaEvent_t e_fork = 0, e_topk = 0, e_side = 0;
    if (!s1) {
        cudaStreamCreateWithFlags(&s1, cudaStreamNonBlocking);
        cudaEventCreateWithFlags(&e_fork, cudaEventDisableTiming);
        cudaEventCreateWithFlags(&e_topk, cudaEventDisableTiming);
        cudaEventCreateWithFlags(&e_side, cudaEventDisableTiming);
    }

    // fork
    cudaEventRecord(e_fork, 0);
    cudaStreamWaitEvent(s1, e_fork, 0);

    // side stream: harris -> topk -> patches_c
    k_harris<<<BN*256, 256, 0, s1>>>(frame);
    k_topk  <<<BN, 256, 0, s1>>>(out_coords);
    cudaEventRecord(e_topk, s1);
    k_patches_c<<<BN*NP, 128, 0, s1>>>(frame, w_c, b_c, out_pc);
    cudaEventRecord(e_side, s1);

    // main stream: conv -> patches_f (needs conv output AND topk coords)
    dim3 gconv(OW/16, OH/4, BN);
    k_conv<<<gconv, 128>>>(frame, w_f, b_f, out_fmap);
    cudaStreamWaitEvent(0, e_topk, 0);
    k_patches_f<<<BN*NP, 128>>>(out_pf);

    // join
    cudaStreamWaitEvent(0, e_side, 0);
}

// round 9
// speedup vs baseline: 1.5386x; 1.5386x over previous
#include <cuda_runtime.h>
#include <math.h>
#include <float.h>

#define BN 8
#define H 480
#define W 640
#define OH 120
#define OW 160
#define CH 128
#define NP 192

typedef unsigned long long u64;

// ---------------- scratch ----------------
__device__ float d_cellval[BN*256];
__device__ int   d_cellxy[BN*256];
__device__ int   d_selxy[BN*NP];
// channel-last fmap copy: [b][oy][ox][ch]
__device__ float d_cl[(size_t)BN*OH*OW*CH];
// pre-paired weights/bias for conv: [tap][pair] and [pair]
__device__ u64 d_wpair[49*64];
__device__ u64 d_bpair[64];

// ---------------- f32x2 helpers ----------------
__device__ __forceinline__ u64 pack2(float lo, float hi) {
    u64 r; asm("mov.b64 %0, {%1, %2};" : "=l"(r) : "f"(lo), "f"(hi)); return r;
}
__device__ __forceinline__ void unpack2(u64 v, float& lo, float& hi) {
    asm("mov.b64 {%0, %1}, %2;" : "=f"(lo), "=f"(hi) : "l"(v));
}
__device__ __forceinline__ u64 ffma2(u64 a, u64 b, u64 c) {
    u64 d; asm("fma.rn.f32x2 %0, %1, %2, %3;" : "=l"(d) : "l"(a), "l"(b), "l"(c)); return d;
}

// ================= K0: weight prep (one-time transpose into pairs) =============
__global__ void k_wprep(const float* __restrict__ wf, const float* __restrict__ bf) {
    int i = blockIdx.x * blockDim.x + threadIdx.x;
    if (i < 49*64) {
        int t = i >> 6, p = i & 63;
        d_wpair[i] = pack2(__ldg(wf + (2*p)*49 + t), __ldg(wf + (2*p+1)*49 + t));
    }
    if (i < 64) d_bpair[i] = pack2(__ldg(bf + 2*i), __ldg(bf + 2*i + 1));
}

// ================= K1: fused harris + per-cell argmax =================
__global__ __launch_bounds__(256) void k_harris(const float* __restrict__ frame) {
    __shared__ float sf[37][48];
    __shared__ float shxx[36][40], shyy[36][40], shxy[36][40];
    __shared__ float sv[256];
    __shared__ int   si[256];

    int blk = blockIdx.x;
    int b = blk >> 8, cell = blk & 255;
    int gh = cell >> 4, gw = cell & 15;
    int gx0 = gw * 40, gy0 = gh * 30;
    int X0 = gx0 - 3, Y0 = gy0 - 3;
    const float* f = frame + (size_t)b * H * W;
    int tid = threadIdx.x;

    for (int i = tid; i < 37 * 47; i += 256) {
        int r = i / 47, c = i - r * 47;
        int x = X0 + c, y = Y0 + r;
        sf[r][c] = (x >= 0 && x < W && y >= 0 && y < H) ? f[y * W + x] : 0.f;
    }
    __syncthreads();

    for (int i = tid; i < 36 * 40; i += 256) {
        int r = i / 40, c = i - r * 40;
        int y = Y0 + r;
        float a = 0.f, bb = 0.f, cc2 = 0.f;
        if (y >= 0 && y < H) {
            bool ylast = (y == H - 1);
            #pragma unroll
            for (int k = 0; k < 7; k++) {
                int cw = c + k;
                int x = X0 + cw;
                if (x >= 0 && x < W) {
                    float dx = (x < W - 1) ? (sf[r][cw+1] - sf[r][cw])
                                           : (sf[r][cw-1] - sf[r][cw-2]);
                    float dy = !ylast ? (sf[r+1][cw] - sf[r][cw])
                                      : (sf[r-1][cw] - sf[r-2][cw]);
                    a   = fmaf(dx, dx, a);
                    bb  = fmaf(dy, dy, bb);
                    cc2 = fmaf(dx, dy, cc2);
                }
            }
        }
        shxx[r][c] = a; shyy[r][c] = bb; shxy[r][c] = cc2;
    }
    __syncthreads();

    float bv = -FLT_MAX;
    int   bi = 0x7FFFFFFF;
    for (int fi = tid; fi < 1200; fi += 256) {
        int py = fi / 40, px = fi - py * 40;
        float a = 0.f, bb = 0.f, cc = 0.f;
        #pragma unroll
        for (int k = 0; k < 7; k++) {
            a  += shxx[py + k][px];
            bb += shyy[py + k][px];
            cc += shxy[py + k][px];
        }
        float Ixx = a / 49.0f, Iyy = bb / 49.0f, Ixy = cc / 49.0f;
        float g = (Ixx * Iyy - Ixy * Ixy) / (Ixx + Iyy + 1e-8f);
        if (g > bv) { bv = g; bi = fi; }
    }
    sv[tid] = bv; si[tid] = bi;
    __syncthreads();
    for (int s = 128; s > 0; s >>= 1) {
        if (tid < s) {
            float v2 = sv[tid + s]; int i2 = si[tid + s];
            if (v2 > sv[tid] || (v2 == sv[tid] && i2 < si[tid])) { sv[tid] = v2; si[tid] = i2; }
        }
        __syncthreads();
    }
    if (tid == 0) {
        int fi = si[0];
        int py = fi / 40, px = fi - py * 40;
        d_cellval[blk] = sv[0];
        d_cellxy[blk]  = ((gy0 + py) << 16) | (gx0 + px);
    }
}

// ================= K2: top-192 by rank count (stable) =================
__global__ void k_topk(float* __restrict__ out_coords) {
    __shared__ float sv[256];
    __shared__ int   sxy[256];
    int b = blockIdx.x, i = threadIdx.x;
    sv[i]  = d_cellval[b*256 + i];
    sxy[i] = d_cellxy[b*256 + i];
    __syncthreads();
    float v = sv[i];
    int rank = 0;
    #pragma unroll 8
    for (int j = 0; j < 256; j++) {
        float vj = sv[j];
        rank += (vj > v) || (vj == v && j < i);
    }
    if (rank < NP) {
        int xy = sxy[i];
        int x = xy & 0xFFFF, y = xy >> 16;
        out_coords[((size_t)b*NP + rank)*2 + 0] = (float)x;
        out_coords[((size_t)b*NP + rank)*2 + 1] = (float)y;
        d_selxy[b*NP + rank] = xy;
    }
}

// ================= K3: conv v9 — occupancy-first =================
// 256 thr = 8 warps. warp: oyr = w&3, chh = w>>2. Thread: ONE channel pair
// p = chh*32+lane, 16 px of one output row. 16 u64 accs -> ~70 regs ->
// 3 blocks/SM (~75% occ). Weights from d_wpair (paired u64, no pack ALU).
#define SO_STRIDE 130

__global__ __launch_bounds__(256, 3) void k_conv(
    const float* __restrict__ frame,
    float* __restrict__ fmap)
{
    __shared__ __align__(16) unsigned char s_mem[35424];
    u64*   s_w   = (u64*)s_mem;                       // 49*64 u64 = 25088 B
    u64*   s_in  = (u64*)(s_mem + 25088);             // 19*68 u64 = 10336 B
    float* s_out = (float*)s_mem;                     // overlay: 4*16*130*4 = 33280 B

    int tid  = threadIdx.x;
    int lane = tid & 31;
    int warp = tid >> 5;
    int oyr  = warp & 3;
    int chh  = warp >> 2;
    int p    = chh * 32 + lane;
    int c0   = 2 * p;

    int ox0 = blockIdx.x * 16;
    int oy0 = blockIdx.y * 4;
    int b   = blockIdx.z;
    const float* f = frame + (size_t)b * H * W;
    int row0 = oy0 * 4 - 3, col0 = ox0 * 4 - 3;

    // coalesced paired-weight copy (LDG.64 -> STS.64)
    for (int i = tid; i < 49*64; i += 256) s_w[i] = d_wpair[i];
    // input window: 19 rows x 67 cols, duplicated (v,v) pairs
    for (int i = tid; i < 19*67; i += 256) {
        int r = i / 67, c = i - r * 67;
        int y = row0 + r, x = col0 + c;
        float v = (y >= 0 && y < H && x >= 0 && x < W) ? f[(size_t)y*W + x] : 0.f;
        s_in[r * 68 + c] = pack2(v, v);
    }
    u64 bias2 = d_bpair[p];
    __syncthreads();

    u64 acc[16];
    #pragma unroll
    for (int i = 0; i < 16; i++) acc[i] = bias2;

    #pragma unroll 1
    for (int ky = 0; ky < 7; ky++) {
        u64 wk[7];
        #pragma unroll
        for (int kx = 0; kx < 7; kx++) wk[kx] = s_w[(ky*7 + kx) * 64 + p];
        const u64* inp = s_in + (oyr * 4 + ky) * 68;
        #pragma unroll
        for (int c = 0; c < 67; c++) {
            u64 v = inp[c];
            int kx1 = c & 3, px1 = c >> 2;
            if (px1 < 16)
                acc[px1] = ffma2(v, wk[kx1], acc[px1]);
            if (kx1 < 3 && c >= 4)
                acc[px1 - 1] = ffma2(v, wk[kx1 + 4], acc[px1 - 1]);
        }
    }

    // relu + channel-last store (coalesced 256B segments per warp per px)
    int oy = oy0 + oyr;
    float lo[16], hi[16];
    #pragma unroll
    for (int px = 0; px < 16; px++) {
        float a0, a1; unpack2(acc[px], a0, a1);
        lo[px] = fmaxf(a0, 0.f); hi[px] = fmaxf(a1, 0.f);
        u64* clp = (u64*)(d_cl + (((size_t)(b*OH + oy))*OW + ox0 + px) * CH);
        clp[p] = pack2(lo[px], hi[px]);
    }

    // stage required layout (px-major, conflict-free u64 writes)
    __syncthreads();
    #pragma unroll
    for (int px = 0; px < 16; px++) {
        u64* po = (u64*)(s_out + (oyr*16 + px) * SO_STRIDE);
        po[p] = pack2(lo[px], hi[px]);
    }
    __syncthreads();

    // coalesced copy-out (reads stride-130: conflict-free)
    for (int i = tid; i < 4 * 128 * 16; i += 256) {
        int px = i & 15;
        int ch = (i >> 4) & 127;
        int r  = i >> 11;
        fmap[(((size_t)(b*CH + ch)) * OH + (oy0 + r)) * OW + ox0 + px] =
            s_out[(r*16 + px) * SO_STRIDE + ch];
    }
}

// ================= K4: patches_f — channel-last coalesced gather =============
__global__ __launch_bounds__(128) void k_patches_f(float* __restrict__ out) {
    __shared__ float s[CH * 49];
    int bp = blockIdx.x;
    int b  = bp / NP;
    int c  = threadIdx.x;
    int xy = d_selxy[bp];
    float fx = (float)(xy & 0xFFFF) * 0.25f;
    float fy = (float)(xy >> 16)    * 0.25f;
    int x0 = (int)floorf(fx);
    int y0 = (int)floorf(fy);
    float wx = fx - (float)x0, wy = fy - (float)y0;
    int gx0 = x0 - 3, gy0 = y0 - 3;

    const float* base = d_cl + (size_t)b * OH * OW * CH + c;

    float v[64];
    #pragma unroll
    for (int pt = 0; pt < 64; pt++) {
        int yy = pt >> 3, xx = pt & 7;
        int gy = gy0 + yy, gx = gx0 + xx;
        bool ok = (gx >= 0) & (gx < OW) & (gy >= 0) & (gy < OH);
        v[pt] = ok ? __ldg(base + ((size_t)gy * OW + gx) * CH) : 0.f;
    }

    float w00 = (1.f - wx) * (1.f - wy);
    float w10 = wx * (1.f - wy);
    float w01 = (1.f - wx) * wy;
    float w11 = wx * wy;

    #pragma unroll
    for (int j = 0; j < 7; j++) {
        #pragma unroll
        for (int i = 0; i < 7; i++) {
            float acc = v[j*8 + i]       * w00
                      + v[j*8 + i + 1]   * w10
                      + v[(j+1)*8 + i]   * w01
                      + v[(j+1)*8 + i+1] * w11;
            s[c * 49 + (j*7 + i)] = acc;
        }
    }
    __syncthreads();

    float* o = out + (size_t)bp * (CH * 49);
    for (int k = threadIdx.x; k < CH * 49; k += 128)
        o[k] = s[k];
}

// ================= K5: patches_c — smem-staged weights =================
__global__ __launch_bounds__(128) void k_patches_c(
    const float* __restrict__ frame,
    const float* __restrict__ wc,
    const float* __restrict__ bc,
    float* __restrict__ out)
{
    __shared__ float s_w[CH * 49];
    __shared__ float s_in[121];
    int bp = blockIdx.x;
    int b  = bp / NP;
    int c  = threadIdx.x;
    int xy = d_selxy[bp];
    float fx = (float)(xy & 0xFFFF) * 0.25f;
    float fy = (float)(xy >> 16)    * 0.25f;
    int x0 = (int)floorf(fx);
    int y0 = (int)floorf(fy);
    float wx = fx - (float)x0, wy = fy - (float)y0;

    const float* f = frame + (size_t)b * H * W;
    int row0 = y0 * 4 - 3, col0 = x0 * 4 - 3;
    for (int i = threadIdx.x; i < CH * 49; i += 128) s_w[i] = __ldg(wc + i);
    for (int i = threadIdx.x; i < 121; i += 128) {
        int r = i / 11, cc = i - r * 11;
        int yyy = row0 + r, xxx = col0 + cc;
        s_in[i] = (yyy >= 0 && yyy < H && xxx >= 0 && xxx < W) ? f[yyy*W + xxx] : 0.f;
    }
    float bias = __ldg(bc + c);
    __syncthreads();

    float wreg[49];
    #pragma unroll
    for (int i = 0; i < 49; i++) wreg[i] = s_w[c*49 + i];

    float wts[4] = { (1.f-wx)*(1.f-wy), wx*(1.f-wy), (1.f-wx)*wy, wx*wy };
    float acc = 0.f;
    #pragma unroll
    for (int n = 0; n < 4; n++) {
        int dxn = n & 1, dyn = n >> 1;
        int xi = x0 + dxn, yi = y0 + dyn;
        if (xi < OW && yi < OH) {
            float v = bias;
            #pragma unroll
            for (int ky = 0; ky < 7; ky++)
                #pragma unroll
                for (int kx = 0; kx < 7; kx++)
                    v = fmaf(s_in[(dyn*4 + ky)*11 + (dxn*4 + kx)], wreg[ky*7 + kx], v);
            v = fmaxf(v, 0.f);
            acc += v * wts[n];
        }
    }
    out[(size_t)bp * CH + c] = acc;
}

// ---------------- launch: fork-join across two streams ---------------------------
extern "C" void kernel_launch(void* const* d_in, const int* in_sizes, int n_in,
                              void* d_out, int out_size) {
    const float* frame = (const float*)d_in[0];
    const float* w_f   = (const float*)d_in[1];
    const float* b_f   = (const float*)d_in[2];
    const float* w_c   = (const float*)d_in[3];
    const float* b_c   = (const float*)d_in[4];

    float* out        = (float*)d_out;
    float* out_coords = out;                                   // 8*192*2
    float* out_pf     = out + 3072;                            // 8*192*128*49
    float* out_pc     = out + 3072 + 9633792;                  // 8*192*128
    float* out_fmap   = out + 3072 + 9633792 + 196608;         // 8*128*120*160

    static cudaStream_t s1 = 0;
    static cudaEvent_t e_fork = 0, e_topk = 0, e_side = 0;
    if (!s1) {
        cudaStreamCreateWithFlags(&s1, cudaStreamNonBlocking);
        cudaEventCreateWithFlags(&e_fork, cudaEventDisableTiming);
        cudaEventCreateWithFlags(&e_topk, cudaEventDisableTiming);
        cudaEventCreateWithFlags(&e_side, cudaEventDisableTiming);
    }

    // fork
    cudaEventRecord(e_fork, 0);
    cudaStreamWaitEvent(s1, e_fork, 0);

    // side stream: harris -> topk -> patches_c
    k_harris<<<BN*256, 256, 0, s1>>>(frame);
    k_topk  <<<BN, 256, 0, s1>>>(out_coords);
    cudaEventRecord(e_topk, s1);
    k_patches_c<<<BN*NP, 128, 0, s1>>>(frame, w_c, b_c, out_pc);
    cudaEventRecord(e_side, s1);

    // main stream: wprep -> conv -> patches_f (needs conv output AND topk coords)
    k_wprep<<<25, 128>>>(w_f, b_f);
    dim3 gconv(OW/16, OH/4, BN);
    k_conv<<<gconv, 256>>>(frame, out_fmap);
    cudaStreamWaitEvent(0, e_topk, 0);
    k_patches_f<<<BN*NP, 128>>>(out_pf);

    // join
    cudaStreamWaitEvent(0, e_side, 0);
}

// round 11
// speedup vs baseline: 1.6598x; 1.0788x over previous
#include <cuda_runtime.h>
#include <cuda_bf16.h>
#include <math.h>
#include <float.h>

#define BN 8
#define H 480
#define W 640
#define OH 120
#define OW 160
#define CH 128
#define NP 192

typedef unsigned long long u64;
typedef unsigned int u32;

// ---------------- scratch ----------------
__device__ float d_cellval[BN*256];
__device__ int   d_cellxy[BN*256];
__device__ int   d_selxy[BN*NP];
// channel-last fmap copy: [b][oy][ox][ch]
__device__ __align__(16) float d_cl[(size_t)BN*OH*OW*CH];
// pre-split bf16 weights, padded [128 ch][72 taps] stored as u32 pairs [128][36]
__device__ u32 d_wAhi32[128*36];
__device__ u32 d_wAlo32[128*36];

// ---------------- helpers ----------------
__device__ __forceinline__ unsigned smem_u32(const void* p) {
    unsigned a;
    asm("{ .reg .u64 t; cvta.to.shared.u64 t, %1; cvt.u32.u64 %0, t; }" : "=r"(a) : "l"(p));
    return a;
}
#define LDM_X4(r0,r1,r2,r3,addr) \
    asm volatile("ldmatrix.sync.aligned.m8n8.x4.shared.b16 {%0,%1,%2,%3}, [%4];" \
        : "=r"(r0),"=r"(r1),"=r"(r2),"=r"(r3) : "r"(addr))
#define LDM_X2(r0,r1,addr) \
    asm volatile("ldmatrix.sync.aligned.m8n8.x2.shared.b16 {%0,%1}, [%2];" \
        : "=r"(r0),"=r"(r1) : "r"(addr))
#define MMA16816(d, a0,a1,a2,a3, b0,b1) \
    asm volatile("mma.sync.aligned.m16n8k16.row.col.f32.bf16.bf16.f32 " \
        "{%0,%1,%2,%3}, {%4,%5,%6,%7}, {%8,%9}, {%0,%1,%2,%3};" \
        : "+f"((d)[0]),"+f"((d)[1]),"+f"((d)[2]),"+f"((d)[3]) \
        : "r"(a0),"r"(a1),"r"(a2),"r"(a3),"r"(b0),"r"(b1))

__device__ __forceinline__ u32 pack_hilo(float v0, float v1) {
    __nv_bfloat162 h2 = __floats2bfloat162_rn(v0, v1);   // x=v0 low, y=v1 high
    return *(u32*)&h2;
}

// ================= K0: weight prep — bf16 hi/lo split, padded [128][72] =========
__global__ void k_wprep(const float* __restrict__ wf) {
    int i = blockIdx.x * blockDim.x + threadIdx.x;   // 128*36
    if (i >= 128*36) return;
    int ch = i / 36, j = i - ch*36;
    int t0 = 2*j, t1 = 2*j + 1;
    float v0 = (t0 < 49) ? __ldg(wf + ch*49 + t0) : 0.f;
    float v1 = (t1 < 49) ? __ldg(wf + ch*49 + t1) : 0.f;
    __nv_bfloat16 h0 = __float2bfloat16_rn(v0), h1 = __float2bfloat16_rn(v1);
    float l0f = v0 - __bfloat162float(h0), l1f = v1 - __bfloat162float(h1);
    d_wAhi32[i] = pack_hilo(__bfloat162float(h0), __bfloat162float(h1));
    d_wAlo32[i] = pack_hilo(l0f, l1f);
}

// ================= K1: fused harris + per-cell argmax =================
__global__ __launch_bounds__(256) void k_harris(const float* __restrict__ frame) {
    __shared__ float sf[37][48];
    __shared__ float shxx[36][40], shyy[36][40], shxy[36][40];
    __shared__ float sv[256];
    __shared__ int   si[256];

    int blk = blockIdx.x;
    int b = blk >> 8, cell = blk & 255;
    int gh = cell >> 4, gw = cell & 15;
    int gx0 = gw * 40, gy0 = gh * 30;
    int X0 = gx0 - 3, Y0 = gy0 - 3;
    const float* f = frame + (size_t)b * H * W;
    int tid = threadIdx.x;

    for (int i = tid; i < 37 * 47; i += 256) {
        int r = i / 47, c = i - r * 47;
        int x = X0 + c, y = Y0 + r;
        sf[r][c] = (x >= 0 && x < W && y >= 0 && y < H) ? f[y * W + x] : 0.f;
    }
    __syncthreads();

    for (int i = tid; i < 36 * 40; i += 256) {
        int r = i / 40, c = i - r * 40;
        int y = Y0 + r;
        float a = 0.f, bb = 0.f, cc2 = 0.f;
        if (y >= 0 && y < H) {
            bool ylast = (y == H - 1);
            #pragma unroll
            for (int k = 0; k < 7; k++) {
                int cw = c + k;
                int x = X0 + cw;
                if (x >= 0 && x < W) {
                    float dx = (x < W - 1) ? (sf[r][cw+1] - sf[r][cw])
                                           : (sf[r][cw-1] - sf[r][cw-2]);
                    float dy = !ylast ? (sf[r+1][cw] - sf[r][cw])
                                      : (sf[r-1][cw] - sf[r-2][cw]);
                    a   = fmaf(dx, dx, a);
                    bb  = fmaf(dy, dy, bb);
                    cc2 = fmaf(dx, dy, cc2);
                }
            }
        }
        shxx[r][c] = a; shyy[r][c] = bb; shxy[r][c] = cc2;
    }
    __syncthreads();

    float bv = -FLT_MAX;
    int   bi = 0x7FFFFFFF;
    for (int fi = tid; fi < 1200; fi += 256) {
        int py = fi / 40, px = fi - py * 40;
        float a = 0.f, bb = 0.f, cc = 0.f;
        #pragma unroll
        for (int k = 0; k < 7; k++) {
            a  += shxx[py + k][px];
            bb += shyy[py + k][px];
            cc += shxy[py + k][px];
        }
        float Ixx = a / 49.0f, Iyy = bb / 49.0f, Ixy = cc / 49.0f;
        float g = (Ixx * Iyy - Ixy * Ixy) / (Ixx + Iyy + 1e-8f);
        if (g > bv) { bv = g; bi = fi; }
    }
    sv[tid] = bv; si[tid] = bi;
    __syncthreads();
    for (int s = 128; s > 0; s >>= 1) {
        if (tid < s) {
            float v2 = sv[tid + s]; int i2 = si[tid + s];
            if (v2 > sv[tid] || (v2 == sv[tid] && i2 < si[tid])) { sv[tid] = v2; si[tid] = i2; }
        }
        __syncthreads();
    }
    if (tid == 0) {
        int fi = si[0];
        int py = fi / 40, px = fi - py * 40;
        d_cellval[blk] = sv[0];
        d_cellxy[blk]  = ((gy0 + py) << 16) | (gx0 + px);
    }
}

// ================= K2: top-192 by rank count (stable) =================
__global__ void k_topk(float* __restrict__ out_coords) {
    __shared__ float sv[256];
    __shared__ int   sxy[256];
    int b = blockIdx.x, i = threadIdx.x;
    sv[i]  = d_cellval[b*256 + i];
    sxy[i] = d_cellxy[b*256 + i];
    __syncthreads();
    float v = sv[i];
    int rank = 0;
    #pragma unroll 8
    for (int j = 0; j < 256; j++) {
        float vj = sv[j];
        rank += (vj > v) || (vj == v && j < i);
    }
    if (rank < NP) {
        int xy = sxy[i];
        int x = xy & 0xFFFF, y = xy >> 16;
        out_coords[((size_t)b*NP + rank)*2 + 0] = (float)x;
        out_coords[((size_t)b*NP + rank)*2 + 1] = (float)y;
        d_selxy[b*NP + rank] = xy;
    }
}

// ================= K3: conv v11 — mma.sync bf16 (3-term hi/lo split) =============
// CTA: 256 thr = 8 warps, tile 4 oy x 32 ox = 128 px, all 128 ch.
// D[128 ch][128 px] = A[128x64] . B[128 px x 64]^T, K padded 49->64.
// Warp (wm, wn): 32 ch x 64 px tile = 2(m16) x 8(n8) frags, 4 k16-steps, 3 terms.
#define BSTRIDE 72                       // bf16 per row (144 B, 36 words)
#define OFF_A_HI  0
#define OFF_A_LO  18432
#define OFF_B_HI  36864
#define OFF_B_LO  55296
#define OFF_IN    73728                  // float[19*132] = 10032 B
#define SMEM_TOT  (OFF_IN + 10032 + 16)
// epilogue stage overlays A/B: 128 px x 132 floats = 67584 B

__global__ __launch_bounds__(256) void k_conv_tc(
    const float* __restrict__ frame,
    const float* __restrict__ bf,
    float* __restrict__ fmap)
{
    extern __shared__ __align__(16) unsigned char smem[];
    unsigned sbase = smem_u32(smem);
    float* s_in = (float*)(smem + OFF_IN);

    int tid  = threadIdx.x;
    int lane = tid & 31;
    int warp = tid >> 5;

    int ox0 = blockIdx.x * 32;
    int oy0 = blockIdx.y * 4;
    int b   = blockIdx.z;
    const float* f = frame + (size_t)b * H * W;

    // ---- prologue: weights (coalesced u32 copy) + input window ----
    {
        u32* aH = (u32*)(smem + OFF_A_HI);
        u32* aL = (u32*)(smem + OFF_A_LO);
        for (int i = tid; i < 128*36; i += 256) { aH[i] = d_wAhi32[i]; aL[i] = d_wAlo32[i]; }
        int row0 = oy0 * 4 - 3, col0 = ox0 * 4 - 3;
        for (int i = tid; i < 19 * 131; i += 256) {
            int r = i / 131, c = i - r * 131;
            int y = row0 + r, x = col0 + c;
            s_in[r * 132 + c] = (y >= 0 && y < H && x >= 0 && x < W) ? f[(size_t)y * W + x] : 0.f;
        }
    }
    __syncthreads();

    // ---- im2col: thread = px (tid < 128); hi/lo bf16 pairs, packed u32 writes ----
    if (tid < 128) {
        int oyr = tid >> 5, oxl = tid & 31;
        u32* bH = (u32*)(smem + OFF_B_HI) + tid * 36;
        u32* bL = (u32*)(smem + OFF_B_LO) + tid * 36;
        const float* base = s_in + oyr * 4 * 132 + oxl * 4;
        #pragma unroll
        for (int j = 0; j < 36; j++) {
            int t0 = 2*j, t1 = 2*j + 1;
            float v0 = 0.f, v1 = 0.f;
            if (t0 < 49) v0 = base[(t0/7) * 132 + (t0%7)];
            if (t1 < 49) v1 = base[(t1/7) * 132 + (t1%7)];
            __nv_bfloat16 h0 = __float2bfloat16_rn(v0), h1 = __float2bfloat16_rn(v1);
            bH[j] = pack_hilo(__bfloat162float(h0), __bfloat162float(h1));
            bL[j] = pack_hilo(v0 - __bfloat162float(h0), v1 - __bfloat162float(h1));
        }
    }
    __syncthreads();

    // ---- MMA main loop ----
    int wm = warp & 3, wn = warp >> 2;
    int m0 = wm * 32;
    int n0 = wn * 64;
    float acc[2][8][4];
    #pragma unroll
    for (int mi = 0; mi < 2; mi++)
        #pragma unroll
        for (int ni = 0; ni < 8; ni++)
            #pragma unroll
            for (int r = 0; r < 4; r++) acc[mi][ni][r] = 0.f;

    // ldmatrix per-lane row offsets (bytes)
    unsigned aRowOff = ((lane & 15) * BSTRIDE + ((lane >> 4) << 3)) * 2;
    unsigned bRowOff = ((lane & 7)  * BSTRIDE + (((lane >> 3) & 1) << 3)) * 2;

    #pragma unroll 1
    for (int term = 0; term < 3; term++) {
        unsigned Aoff = (term == 2) ? OFF_A_LO : OFF_A_HI;
        unsigned Boff = (term == 1) ? OFF_B_LO : OFF_B_HI;
        unsigned aBase = sbase + Aoff + m0 * (BSTRIDE*2) + aRowOff;
        unsigned bBase = sbase + Boff + n0 * (BSTRIDE*2) + bRowOff;
        #pragma unroll
        for (int ks = 0; ks < 4; ks++) {
            unsigned kb = ks * 32;                 // 16 bf16 = 32 bytes
            u32 a0,a1,a2,a3, a4,a5,a6,a7;
            LDM_X4(a0,a1,a2,a3, aBase + kb);
            LDM_X4(a4,a5,a6,a7, aBase + 16*(BSTRIDE*2) + kb);
            #pragma unroll
            for (int ni = 0; ni < 8; ni++) {
                u32 b0, b1;
                LDM_X2(b0, b1, bBase + ni * 8 * (BSTRIDE*2) + kb);
                MMA16816(acc[0][ni], a0,a1,a2,a3, b0,b1);
                MMA16816(acc[1][ni], a4,a5,a6,a7, b0,b1);
            }
        }
    }
    __syncthreads();   // A/B dead; stage overlays them

    // ---- epilogue: bias + relu; fmap direct STG.64; d_cl via stride-132 stage ----
    float* stg = (float*)smem;           // [px][132]
    int l4 = lane >> 2, l2 = (lane & 3) * 2;
    #pragma unroll
    for (int mi = 0; mi < 2; mi++) {
        int ch0 = m0 + mi*16 + l4;
        float bv0 = __ldg(bf + ch0);
        float bv1 = __ldg(bf + ch0 + 8);
        #pragma unroll
        for (int ni = 0; ni < 8; ni++) {
            int px = n0 + ni*8 + l2;
            int oy = oy0 + (px >> 5), ox = ox0 + (px & 31);
            float v00 = fmaxf(acc[mi][ni][0] + bv0, 0.f);
            float v01 = fmaxf(acc[mi][ni][1] + bv0, 0.f);
            float v10 = fmaxf(acc[mi][ni][2] + bv1, 0.f);
            float v11 = fmaxf(acc[mi][ni][3] + bv1, 0.f);
            *(float2*)(fmap + (((size_t)(b*CH + ch0    ))*OH + oy)*OW + ox) = make_float2(v00, v01);
            *(float2*)(fmap + (((size_t)(b*CH + ch0 + 8))*OH + oy)*OW + ox) = make_float2(v10, v11);
            stg[ px    * 132 + ch0    ] = v00;
            stg[(px+1) * 132 + ch0    ] = v01;
            stg[ px    * 132 + ch0 + 8] = v10;
            stg[(px+1) * 132 + ch0 + 8] = v11;
        }
    }
    __syncthreads();

    // d_cl copy: float4, coalesced 512B per warp
    for (int i = tid; i < 128 * 32; i += 256) {
        int px = i >> 5, c4 = (i & 31) * 4;
        float4 v = *(const float4*)(stg + px * 132 + c4);
        int oy = oy0 + (px >> 5), ox = ox0 + (px & 31);
        *(float4*)(d_cl + (((size_t)(b*OH + oy))*OW + ox)*CH + c4) = v;
    }
}

// ================= K4: patches_f — channel-last coalesced gather =============
__global__ __launch_bounds__(128) void k_patches_f(float* __restrict__ out) {
    __shared__ float s[CH * 49];
    int bp = blockIdx.x;
    int b  = bp / NP;
    int c  = threadIdx.x;
    int xy = d_selxy[bp];
    float fx = (float)(xy & 0xFFFF) * 0.25f;
    float fy = (float)(xy >> 16)    * 0.25f;
    int x0 = (int)floorf(fx);
    int y0 = (int)floorf(fy);
    float wx = fx - (float)x0, wy = fy - (float)y0;
    int gx0 = x0 - 3, gy0 = y0 - 3;

    const float* base = d_cl + (size_t)b * OH * OW * CH + c;

    float v[64];
    #pragma unroll
    for (int pt = 0; pt < 64; pt++) {
        int yy = pt >> 3, xx = pt & 7;
        int gy = gy0 + yy, gx = gx0 + xx;
        bool ok = (gx >= 0) & (gx < OW) & (gy >= 0) & (gy < OH);
        v[pt] = ok ? __ldg(base + ((size_t)gy * OW + gx) * CH) : 0.f;
    }

    float w00 = (1.f - wx) * (1.f - wy);
    float w10 = wx * (1.f - wy);
    float w01 = (1.f - wx) * wy;
    float w11 = wx * wy;

    #pragma unroll
    for (int j = 0; j < 7; j++) {
        #pragma unroll
        for (int i = 0; i < 7; i++) {
            float acc = v[j*8 + i]       * w00
                      + v[j*8 + i + 1]   * w10
                      + v[(j+1)*8 + i]   * w01
                      + v[(j+1)*8 + i+1] * w11;
            s[c * 49 + (j*7 + i)] = acc;
        }
    }
    __syncthreads();

    float* o = out + (size_t)bp * (CH * 49);
    for (int k = threadIdx.x; k < CH * 49; k += 128)
        o[k] = s[k];
}

// ================= K5: patches_c — smem-staged weights =================
__global__ __launch_bounds__(128) void k_patches_c(
    const float* __restrict__ frame,
    const float* __restrict__ wc,
    const float* __restrict__ bc,
    float* __restrict__ out)
{
    __shared__ float s_w[CH * 49];
    __shared__ float s_in2[121];
    int bp = blockIdx.x;
    int b  = bp / NP;
    int c  = threadIdx.x;
    int xy = d_selxy[bp];
    float fx = (float)(xy & 0xFFFF) * 0.25f;
    float fy = (float)(xy >> 16)    * 0.25f;
    int x0 = (int)floorf(fx);
    int y0 = (int)floorf(fy);
    float wx = fx - (float)x0, wy = fy - (float)y0;

    const float* f = frame + (size_t)b * H * W;
    int row0 = y0 * 4 - 3, col0 = x0 * 4 - 3;
    for (int i = threadIdx.x; i < CH * 49; i += 128) s_w[i] = __ldg(wc + i);
    for (int i = threadIdx.x; i < 121; i += 128) {
        int r = i / 11, cc = i - r * 11;
        int yyy = row0 + r, xxx = col0 + cc;
        s_in2[i] = (yyy >= 0 && yyy < H && xxx >= 0 && xxx < W) ? f[yyy*W + xxx] : 0.f;
    }
    float bias = __ldg(bc + c);
    __syncthreads();

    float wreg[49];
    #pragma unroll
    for (int i = 0; i < 49; i++) wreg[i] = s_w[c*49 + i];

    float wts[4] = { (1.f-wx)*(1.f-wy), wx*(1.f-wy), (1.f-wx)*wy, wx*wy };
    float acc = 0.f;
    #pragma unroll
    for (int n = 0; n < 4; n++) {
        int dxn = n & 1, dyn = n >> 1;
        int xi = x0 + dxn, yi = y0 + dyn;
        if (xi < OW && yi < OH) {
            float v = bias;
            #pragma unroll
            for (int ky = 0; ky < 7; ky++)
                #pragma unroll
                for (int kx = 0; kx < 7; kx++)
                    v = fmaf(s_in2[(dyn*4 + ky)*11 + (dxn*4 + kx)], wreg[ky*7 + kx], v);
            v = fmaxf(v, 0.f);
            acc += v * wts[n];
        }
    }
    out[(size_t)bp * CH + c] = acc;
}

// ---------------- launch: fork-join across two streams ---------------------------
extern "C" void kernel_launch(void* const* d_in, const int* in_sizes, int n_in,
                              void* d_out, int out_size) {
    const float* frame = (const float*)d_in[0];
    const float* w_f   = (const float*)d_in[1];
    const float* b_f   = (const float*)d_in[2];
    const float* w_c   = (const float*)d_in[3];
    const float* b_c   = (const float*)d_in[4];

    float* out        = (float*)d_out;
    float* out_coords = out;                                   // 8*192*2
    float* out_pf     = out + 3072;                            // 8*192*128*49
    float* out_pc     = out + 3072 + 9633792;                  // 8*192*128
    float* out_fmap   = out + 3072 + 9633792 + 196608;         // 8*128*120*160

    static cudaStream_t s1 = 0;
    static cudaEvent_t e_fork = 0, e_topk = 0, e_side = 0;
    if (!s1) {
        cudaStreamCreateWithFlags(&s1, cudaStreamNonBlocking);
        cudaEventCreateWithFlags(&e_fork, cudaEventDisableTiming);
        cudaEventCreateWithFlags(&e_topk, cudaEventDisableTiming);
        cudaEventCreateWithFlags(&e_side, cudaEventDisableTiming);
        cudaFuncSetAttribute(k_conv_tc, cudaFuncAttributeMaxDynamicSharedMemorySize, SMEM_TOT);
    }

    // fork
    cudaEventRecord(e_fork, 0);
    cudaStreamWaitEvent(s1, e_fork, 0);

    // side stream: harris -> topk -> patches_c
    k_harris<<<BN*256, 256, 0, s1>>>(frame);
    k_topk  <<<BN, 256, 0, s1>>>(out_coords);
    cudaEventRecord(e_topk, s1);
    k_patches_c<<<BN*NP, 128, 0, s1>>>(frame, w_c, b_c, out_pc);
    cudaEventRecord(e_side, s1);

    // main stream: wprep -> conv(tensor) -> patches_f
    k_wprep<<<36, 128>>>(w_f);
    dim3 gconv(OW/32, OH/4, BN);
    k_conv_tc<<<gconv, 256, SMEM_TOT>>>(frame, b_f, out_fmap);
    cudaStreamWaitEvent(0, e_topk, 0);
    k_patches_f<<<BN*NP, 128>>>(out_pf);

    // join
    cudaStreamWaitEvent(0, e_side, 0);
}